// round 6
// baseline (speedup 1.0000x reference)
#include <cuda_runtime.h>

// Problem constants (fixed by the dataset shapes)
#define DIMS 1024           // embedding dim, fp32
#define VECS_PER_ROW 256    // 1024 floats / 4 per float4
#define MAX_PAIRS 8192
#define VOCAB 50257

#define EPS 1e-8f
#define WEIGHT 0.01f

// Allocation-free scratch
__device__ float g_partial[MAX_PAIRS];      // per-pair (1 - sim)
__device__ unsigned int g_ticket = 0;       // auto-wrapping CTA-completion counter

// Fused kernel: one CTA per pair computes (1 - cosine_sim); the LAST CTA to
// finish reduces all partials to the final scalar (fixed-order => deterministic).
__global__ __launch_bounds__(VECS_PER_ROW) void anchor_loss_kernel(
    const float* __restrict__ W,
    const int* __restrict__ archaic_idx,
    const int* __restrict__ modern_idx,
    float* __restrict__ out,
    int n_pairs)
{
    const int p = blockIdx.x;
    const int t = threadIdx.x;
    const int warp = t >> 5;
    const int lane = t & 31;

    int ia = __ldg(archaic_idx + p);
    int im = __ldg(modern_idx + p);
    ia = min(max(ia, 0), VOCAB - 1);
    im = min(max(im, 0), VOCAB - 1);

    const float4* __restrict__ a4 =
        reinterpret_cast<const float4*>(W + (size_t)ia * DIMS);
    const float4* __restrict__ m4 =
        reinterpret_cast<const float4*>(W + (size_t)im * DIMS);

    const float4 av = a4[t];
    const float4 mv = m4[t];

    float dot = av.x * mv.x + av.y * mv.y + av.z * mv.z + av.w * mv.w;
    float na  = av.x * av.x + av.y * av.y + av.z * av.z + av.w * av.w;
    float nm  = mv.x * mv.x + mv.y * mv.y + mv.z * mv.z + mv.w * mv.w;

    #pragma unroll
    for (int off = 16; off > 0; off >>= 1) {
        dot += __shfl_down_sync(0xFFFFFFFFu, dot, off);
        na  += __shfl_down_sync(0xFFFFFFFFu, na,  off);
        nm  += __shfl_down_sync(0xFFFFFFFFu, nm,  off);
    }

    __shared__ float s_dot[8], s_na[8], s_nm[8];
    __shared__ bool  s_last;
    if (lane == 0) {
        s_dot[warp] = dot;
        s_na[warp]  = na;
        s_nm[warp]  = nm;
    }
    __syncthreads();

    if (warp == 0) {
        float d = (lane < 8) ? s_dot[lane] : 0.0f;
        float a = (lane < 8) ? s_na[lane]  : 0.0f;
        float m = (lane < 8) ? s_nm[lane]  : 0.0f;
        #pragma unroll
        for (int off = 4; off > 0; off >>= 1) {
            d += __shfl_down_sync(0xFFFFFFFFu, d, off);
            a += __shfl_down_sync(0xFFFFFFFFu, a, off);
            m += __shfl_down_sync(0xFFFFFFFFu, m, off);
        }
        if (lane == 0) {
            const float den = fmaxf(sqrtf(a), EPS) * fmaxf(sqrtf(m), EPS);
            g_partial[p] = 1.0f - d / den;

            // Publish the partial, then take a ticket. atomicInc wraps to 0
            // at n_pairs-1, so the counter self-resets for graph replay.
            __threadfence();
            const unsigned ticket = atomicInc(&g_ticket, (unsigned)n_pairs - 1u);
            s_last = (ticket == (unsigned)n_pairs - 1u);
        }
    }
    __syncthreads();

    // Last CTA: deterministic fixed-order reduction of all partials (L2-hot).
    if (s_last) {
        float s = 0.0f;
        for (int i = t; i < n_pairs; i += VECS_PER_ROW)
            s += g_partial[i];

        #pragma unroll
        for (int off = 16; off > 0; off >>= 1)
            s += __shfl_down_sync(0xFFFFFFFFu, s, off);

        if (lane == 0) s_dot[warp] = s;   // reuse smem
        __syncthreads();

        if (warp == 0) {
            s = (lane < 8) ? s_dot[lane] : 0.0f;
            #pragma unroll
            for (int off = 4; off > 0; off >>= 1)
                s += __shfl_down_sync(0xFFFFFFFFu, s, off);
            if (lane == 0)
                out[0] = WEIGHT * (s / (float)n_pairs);
        }
    }
}

extern "C" void kernel_launch(void* const* d_in, const int* in_sizes, int n_in,
                              void* d_out, int out_size)
{
    const float* W  = (const float*)d_in[0];   // [50257, 1024] fp32
    const int*   ai = (const int*)d_in[1];     // [n_pairs] int32
    const int*   mi = (const int*)d_in[2];     // [n_pairs] int32
    float* out = (float*)d_out;

    int n_pairs = in_sizes[1];
    if (n_pairs > MAX_PAIRS) n_pairs = MAX_PAIRS;
    if (n_pairs < 1) n_pairs = 1;

    anchor_loss_kernel<<<n_pairs, VECS_PER_ROW>>>(W, ai, mi, out, n_pairs);
}

// round 9
// speedup vs baseline: 1.3810x; 1.3810x over previous
#include <cuda_runtime.h>
#include <cstdint>

// Problem constants (fixed by the dataset shapes)
#define DIMS 1024            // embedding dim, fp32
#define V4_PER_ROW 256       // 1024 / 4
#define V4_PER_LANE 8        // 256 float4 / 32 lanes
#define PAIRS_PER_CTA 8      // one pair per warp
#define CTA_THREADS 256
#define MAX_CTAS 1024
#define VOCAB 50257

#define EPS 1e-8f
#define WEIGHT 0.01f

// Allocation-free scratch
__device__ float g_partial[MAX_CTAS];     // per-CTA sum of (1 - sim)
__device__ unsigned int g_ticket = 0;     // wraps to 0 each launch -> graph-safe

// acq_rel device-scope atomicInc: release orders our prior st.cg, acquire on
// the winning (last) CTA makes everyone else's st.cg visible. No MEMBAR, no
// CCTL.IVALL L1 flush (unlike __threadfence()).
__device__ __forceinline__ unsigned atomic_inc_acqrel(unsigned* addr, unsigned wrap)
{
    unsigned old;
    asm volatile("atom.acq_rel.gpu.global.inc.u32 %0, [%1], %2;"
                 : "=r"(old) : "l"(addr), "r"(wrap) : "memory");
    return old;
}

__global__ __launch_bounds__(CTA_THREADS) void anchor_loss_kernel(
    const float* __restrict__ W,
    const int* __restrict__ archaic_idx,
    const int* __restrict__ modern_idx,
    float* __restrict__ out,
    int n_pairs, int n_ctas)
{
    const int warp = threadIdx.x >> 5;
    const int lane = threadIdx.x & 31;
    const int p    = blockIdx.x * PAIRS_PER_CTA + warp;

    __shared__ float s_loss[PAIRS_PER_CTA];
    __shared__ bool  s_last;

    float dot = 0.0f, na = 0.0f, nm = 0.0f;

    if (p < n_pairs) {
        int ia = __ldg(archaic_idx + p);
        int im = __ldg(modern_idx + p);
        ia = min(max(ia, 0), VOCAB - 1);
        im = min(max(im, 0), VOCAB - 1);

        const float4* __restrict__ a4 =
            reinterpret_cast<const float4*>(W + (size_t)ia * DIMS) + lane;
        const float4* __restrict__ m4 =
            reinterpret_cast<const float4*>(W + (size_t)im * DIMS) + lane;

        // Two chunks of (4 a-loads + 4 m-loads): 8 independent LDG.128 in
        // flight per chunk, modest register footprint.
        #pragma unroll
        for (int c = 0; c < 2; c++) {
            float4 av[4], mv[4];
            #pragma unroll
            for (int i = 0; i < 4; i++) av[i] = a4[(c * 4 + i) * 32];
            #pragma unroll
            for (int i = 0; i < 4; i++) mv[i] = m4[(c * 4 + i) * 32];
            #pragma unroll
            for (int i = 0; i < 4; i++) {
                dot = fmaf(av[i].x, mv[i].x, fmaf(av[i].y, mv[i].y,
                      fmaf(av[i].z, mv[i].z, fmaf(av[i].w, mv[i].w, dot))));
                na  = fmaf(av[i].x, av[i].x, fmaf(av[i].y, av[i].y,
                      fmaf(av[i].z, av[i].z, fmaf(av[i].w, av[i].w, na))));
                nm  = fmaf(mv[i].x, mv[i].x, fmaf(mv[i].y, mv[i].y,
                      fmaf(mv[i].z, mv[i].z, fmaf(mv[i].w, mv[i].w, nm))));
            }
        }
    }

    // Warp-level reduce (3 values, 5 rounds)
    #pragma unroll
    for (int off = 16; off > 0; off >>= 1) {
        dot += __shfl_down_sync(0xFFFFFFFFu, dot, off);
        na  += __shfl_down_sync(0xFFFFFFFFu, na,  off);
        nm  += __shfl_down_sync(0xFFFFFFFFu, nm,  off);
    }

    if (lane == 0) {
        if (p < n_pairs) {
            const float den = fmaxf(sqrtf(na), EPS) * fmaxf(sqrtf(nm), EPS);
            s_loss[warp] = 1.0f - dot / den;
        } else {
            s_loss[warp] = 0.0f;
        }
    }
    __syncthreads();

    // Warp 0: combine the 8 per-pair losses, publish CTA partial, take ticket.
    if (warp == 0) {
        float c = (lane < PAIRS_PER_CTA) ? s_loss[lane] : 0.0f;
        #pragma unroll
        for (int off = 4; off > 0; off >>= 1)
            c += __shfl_down_sync(0xFFFFFFFFu, c, off);
        if (lane == 0) {
            __stcg(&g_partial[blockIdx.x], c);                 // straight to L2
            const unsigned t = atomic_inc_acqrel(&g_ticket, (unsigned)n_ctas - 1u);
            s_last = (t == (unsigned)n_ctas - 1u);
        }
    }
    __syncthreads();

    // Last CTA: deterministic fixed-order reduction of per-CTA partials.
    if (s_last) {
        float s = 0.0f;
        for (int i = threadIdx.x; i < n_ctas; i += CTA_THREADS)
            s += __ldcg(&g_partial[i]);                        // L2-direct

        #pragma unroll
        for (int off = 16; off > 0; off >>= 1)
            s += __shfl_down_sync(0xFFFFFFFFu, s, off);

        if (lane == 0) s_loss[warp] = s;
        __syncthreads();

        if (warp == 0) {
            s = (lane < 8) ? s_loss[lane] : 0.0f;
            #pragma unroll
            for (int off = 4; off > 0; off >>= 1)
                s += __shfl_down_sync(0xFFFFFFFFu, s, off);
            if (lane == 0)
                out[0] = WEIGHT * (s / (float)n_pairs);
        }
    }
}

extern "C" void kernel_launch(void* const* d_in, const int* in_sizes, int n_in,
                              void* d_out, int out_size)
{
    const float* W  = (const float*)d_in[0];   // [50257, 1024] fp32
    const int*   ai = (const int*)d_in[1];     // [n_pairs] int32
    const int*   mi = (const int*)d_in[2];     // [n_pairs] int32
    float* out = (float*)d_out;

    int n_pairs = in_sizes[1];
    if (n_pairs < 1) n_pairs = 1;

    int n_ctas = (n_pairs + PAIRS_PER_CTA - 1) / PAIRS_PER_CTA;
    if (n_ctas > MAX_CTAS) n_ctas = MAX_CTAS;   // 4096 pairs -> 512 CTAs

    anchor_loss_kernel<<<n_ctas, CTA_THREADS>>>(W, ai, mi, out, n_pairs, n_ctas);
}